// round 2
// baseline (speedup 1.0000x reference)
#include <cuda_runtime.h>

// LIF layer scan: B=64, F=512, L=1024.
// rows = B*F = 32768 independent sequences, sequential scan over L.
// Output: z history then s history, each rows*L floats.

#define L_DIM 1024
#define BR    128       // rows per block (= threads per block)
#define TT    32        // time-tile width
#define NT    (L_DIM / TT)

__global__ __launch_bounds__(BR) void lif_kernel(const float* __restrict__ I,
                                                 float* __restrict__ Z,
                                                 float* __restrict__ S) {
    __shared__ float sI[BR][TT + 1];   // pad -> conflict-free column reads
    __shared__ float sZ[BR][TT + 1];

    const int  t       = threadIdx.x;
    const long rowBase = (long)blockIdx.x * BR;

    // alpha = float(exp(-DT/TAU)) = float(exp(-1/3))
    const float alpha = 0.71653131057378925043f;
    const float omal  = 1.0f - alpha;
    const float thr   = 0.25f;
    const float beta  = 10.0f;

    float v = 0.0f;  // membrane potential for row (rowBase + t)

    for (int tile = 0; tile < NT; ++tile) {
        const long gbase = rowBase * L_DIM + (long)tile * TT;

        // ---- coalesced vectorized load: 128x32 tile = 1024 float4 ----
        // float4 index e4 = k*BR + t ; r = e4/8 ; c4 = e4%8
        #pragma unroll
        for (int k = 0; k < (BR * TT / 4) / BR; ++k) {   // 8 iterations
            int e4 = k * BR + t;
            int r  = e4 >> 3;
            int c4 = (e4 & 7) << 2;
            float4 val = *reinterpret_cast<const float4*>(&I[gbase + (long)r * L_DIM + c4]);
            sI[r][c4 + 0] = val.x;
            sI[r][c4 + 1] = val.y;
            sI[r][c4 + 2] = val.z;
            sI[r][c4 + 3] = val.w;
        }
        __syncthreads();

        // ---- sequential scan of TT steps for this thread's row ----
        #pragma unroll
        for (int c = 0; c < TT; ++c) {
            float i_t = sI[t][c];
            // v_pre = alpha*v + (1-alpha)*i  (no fma contraction, match XLA order)
            float vp = __fadd_rn(__fmul_rn(alpha, v), __fmul_rn(omal, i_t));
            float z  = __fmul_rn(beta, __fsub_rn(vp, thr));
            v = (vp >= thr) ? 0.0f : vp;   // == vp * (1 - s)
            sZ[t][c] = z;
        }
        __syncthreads();

        // ---- coalesced vectorized store of z and s (s = z >= 0) ----
        #pragma unroll
        for (int k = 0; k < (BR * TT / 4) / BR; ++k) {   // 8 iterations
            int e4 = k * BR + t;
            int r  = e4 >> 3;
            int c4 = (e4 & 7) << 2;
            float4 z4;
            z4.x = sZ[r][c4 + 0];
            z4.y = sZ[r][c4 + 1];
            z4.z = sZ[r][c4 + 2];
            z4.w = sZ[r][c4 + 3];
            float4 s4;
            s4.x = (z4.x >= 0.0f) ? 1.0f : 0.0f;
            s4.y = (z4.y >= 0.0f) ? 1.0f : 0.0f;
            s4.z = (z4.z >= 0.0f) ? 1.0f : 0.0f;
            s4.w = (z4.w >= 0.0f) ? 1.0f : 0.0f;
            long g = gbase + (long)r * L_DIM + c4;
            *reinterpret_cast<float4*>(&Z[g]) = z4;
            *reinterpret_cast<float4*>(&S[g]) = s4;
        }
        // NOTE: no third sync needed. Next tile's load writes sI (disjoint from
        // sZ reads above); next tile's compute (which writes sZ) is fenced from
        // these sZ reads by the __syncthreads() after the next load.
    }
}

extern "C" void kernel_launch(void* const* d_in, const int* in_sizes, int n_in,
                              void* d_out, int out_size) {
    const float* I = (const float*)d_in[0];
    float* out = (float*)d_out;
    const int n    = in_sizes[0];        // B*F*L = 33554432
    const int rows = n / L_DIM;          // 32768
    float* Z = out;                      // z history first
    float* S = out + n;                  // then s history
    lif_kernel<<<rows / BR, BR>>>(I, Z, S);
}

// round 5
// speedup vs baseline: 1.6420x; 1.6420x over previous
#include <cuda_runtime.h>
#include <cstdint>

// LIF layer scan: B=64, F=512, L=1024.
// rows = B*F = 32768 independent sequences, sequential scan over L.
// Output: z history then s history, each rows*L floats.
//
// One thread per row, 1 warp per block, 1024 blocks (near-perfect SM balance).
// Input tiles double-buffered via cp.async (16B, SMEM row stride 144B = 9*16
// so every destination is 16B-aligned). All SMEM accesses are 128-bit and
// bank-conflict-free at stride-36-floats. Streaming (.cs) output stores.

#define L_DIM 1024
#define BR    32        // rows per block (= threads per block, one warp)
#define TT    32        // time-tile width
#define NT    (L_DIM / TT)
#define STRD  36        // smem row stride in floats: 144B, 16B-aligned & conflict-free for float4

__device__ __forceinline__ void cp_async16(uint32_t smem_dst, const void* gsrc) {
    asm volatile("cp.async.cg.shared.global [%0], [%1], 16;\n"
                 :: "r"(smem_dst), "l"(gsrc));
}
__device__ __forceinline__ void cp_commit() {
    asm volatile("cp.async.commit_group;\n");
}
template <int N>
__device__ __forceinline__ void cp_wait() {
    asm volatile("cp.async.wait_group %0;\n" :: "n"(N));
}

__global__ __launch_bounds__(BR) void lif_kernel(const float* __restrict__ I,
                                                 float* __restrict__ Z,
                                                 float* __restrict__ S) {
    __shared__ __align__(16) float sI[2][BR][STRD];   // double-buffered input tile
    __shared__ __align__(16) float sZ[BR][STRD];      // z staging for coalesced store

    const int  t       = threadIdx.x;
    const long rowBase = (long)blockIdx.x * BR;

    // alpha = float(exp(-DT/TAU)) = float(exp(-1/3))
    const float alpha = 0.71653131057378925043f;
    const float omal  = 1.0f - alpha;
    const float thr   = 0.25f;
    const float beta  = 10.0f;

    float v = 0.0f;  // membrane potential for row (rowBase + t)

    // Per-thread load slice: 8 x float4 per tile.
    // e4 = k*BR + t ; r = e4/8 ; c4 = (e4%8)*4 -> 8 consecutive threads fetch
    // one row's 128 contiguous bytes (fully coalesced 128B lines).

    // ---- prologue: issue tile 0 into buffer 0 ----
    {
        const float* gb = I + rowBase * L_DIM;
        #pragma unroll
        for (int k = 0; k < 8; ++k) {
            int e4 = k * BR + t;
            int r  = e4 >> 3;
            int c4 = (e4 & 7) << 2;
            uint32_t dst = (uint32_t)__cvta_generic_to_shared(&sI[0][r][c4]);
            cp_async16(dst, gb + (long)r * L_DIM + c4);
        }
        cp_commit();
    }

    #pragma unroll 1
    for (int tile = 0; tile < NT; ++tile) {
        const int  cur   = tile & 1;
        const long gbase = rowBase * L_DIM + (long)tile * TT;

        // ---- issue loads for next tile into the other buffer ----
        if (tile + 1 < NT) {
            const float* gb = I + gbase + TT;
            #pragma unroll
            for (int k = 0; k < 8; ++k) {
                int e4 = k * BR + t;
                int r  = e4 >> 3;
                int c4 = (e4 & 7) << 2;
                uint32_t dst = (uint32_t)__cvta_generic_to_shared(&sI[cur ^ 1][r][c4]);
                cp_async16(dst, gb + (long)r * L_DIM + c4);
            }
            cp_commit();
            cp_wait<1>();   // current tile's group complete; next still in flight
        } else {
            cp_wait<0>();
        }
        __syncwarp();

        // ---- sequential scan of TT steps, consuming/producing float4 chunks ----
        #pragma unroll
        for (int c = 0; c < TT; c += 4) {
            float4 i4 = *reinterpret_cast<const float4*>(&sI[cur][t][c]);
            float4 z4;
            // step x
            float vp = __fadd_rn(__fmul_rn(alpha, v), __fmul_rn(omal, i4.x));
            z4.x = __fmul_rn(beta, __fsub_rn(vp, thr));
            v = (vp >= thr) ? 0.0f : vp;
            // step y
            vp = __fadd_rn(__fmul_rn(alpha, v), __fmul_rn(omal, i4.y));
            z4.y = __fmul_rn(beta, __fsub_rn(vp, thr));
            v = (vp >= thr) ? 0.0f : vp;
            // step z
            vp = __fadd_rn(__fmul_rn(alpha, v), __fmul_rn(omal, i4.z));
            z4.z = __fmul_rn(beta, __fsub_rn(vp, thr));
            v = (vp >= thr) ? 0.0f : vp;
            // step w
            vp = __fadd_rn(__fmul_rn(alpha, v), __fmul_rn(omal, i4.w));
            z4.w = __fmul_rn(beta, __fsub_rn(vp, thr));
            v = (vp >= thr) ? 0.0f : vp;

            *reinterpret_cast<float4*>(&sZ[t][c]) = z4;
        }
        __syncwarp();

        // ---- coalesced streaming store of z and s (s = z >= 0) ----
        #pragma unroll
        for (int k = 0; k < 8; ++k) {
            int e4 = k * BR + t;
            int r  = e4 >> 3;
            int c4 = (e4 & 7) << 2;
            float4 z4 = *reinterpret_cast<const float4*>(&sZ[r][c4]);
            float4 s4;
            s4.x = (z4.x >= 0.0f) ? 1.0f : 0.0f;
            s4.y = (z4.y >= 0.0f) ? 1.0f : 0.0f;
            s4.z = (z4.z >= 0.0f) ? 1.0f : 0.0f;
            s4.w = (z4.w >= 0.0f) ? 1.0f : 0.0f;
            long g = gbase + (long)r * L_DIM + c4;
            __stcs(reinterpret_cast<float4*>(&Z[g]), z4);
            __stcs(reinterpret_cast<float4*>(&S[g]), s4);
        }
        __syncwarp();   // stores read sZ; next tile's compute rewrites it
    }
}

extern "C" void kernel_launch(void* const* d_in, const int* in_sizes, int n_in,
                              void* d_out, int out_size) {
    const float* I = (const float*)d_in[0];
    float* out = (float*)d_out;
    const int n    = in_sizes[0];        // B*F*L = 33554432
    const int rows = n / L_DIM;          // 32768
    float* Z = out;                      // z history first
    float* S = out + n;                  // then s history
    lif_kernel<<<rows / BR, BR>>>(I, Z, S);
}